// round 15
// baseline (speedup 1.0000x reference)
#include <cuda_runtime.h>
#include <cuda_fp16.h>
#include <cstdint>

#define NN 50000
#define NE 1600000
#define NB 196                  // ceil(NN/256)
#define FULLMASK 0xffffffffu

// ---------------- HMMA (mma.sync) helpers — portable sm_80+ features ----------------
__device__ __forceinline__ uint32_t smem_to_u32(const void* p) {
    uint32_t a;
    asm("{ .reg .u64 t; cvta.to.shared.u64 t, %1; cvt.u32.u64 %0, t; }" : "=r"(a) : "l"(p));
    return a;
}
#define LDSM_X4(r0, r1, r2, r3, addr) \
    asm volatile("ldmatrix.sync.aligned.m8n8.x4.shared.b16 {%0,%1,%2,%3}, [%4];" \
                 : "=r"(r0), "=r"(r1), "=r"(r2), "=r"(r3) : "r"(addr))
#define LDSM_X4T(r0, r1, r2, r3, addr) \
    asm volatile("ldmatrix.sync.aligned.m8n8.x4.trans.shared.b16 {%0,%1,%2,%3}, [%4];" \
                 : "=r"(r0), "=r"(r1), "=r"(r2), "=r"(r3) : "r"(addr))

__device__ __forceinline__ void mma16816(float* c, uint32_t a0, uint32_t a1, uint32_t a2,
                                         uint32_t a3, uint32_t b0, uint32_t b1) {
    asm volatile(
        "mma.sync.aligned.m16n8k16.row.col.f32.f16.f16.f32 "
        "{%0,%1,%2,%3}, {%4,%5,%6,%7}, {%8,%9}, {%0,%1,%2,%3};"
        : "+f"(c[0]), "+f"(c[1]), "+f"(c[2]), "+f"(c[3])
        : "r"(a0), "r"(a1), "r"(a2), "r"(a3), "r"(b0), "r"(b1));
}

#define HM_A_OFF 0
#define HM_B_OFF (128 * 272)
#define HM_SMEM_TOTAL (2 * 128 * 272)

// ---------------- scratch ----------------
__device__ __align__(16) float g_h[(size_t)NN * 256];
__device__ __align__(16) float g_x1[(size_t)NN * 128];
__device__ __align__(16) float g_x2[(size_t)NN * 128];
__device__ __align__(16) float g_skip[(size_t)NN * 128];
__device__ __align__(16) float g_as[NN * 4];
__device__ __align__(16) float g_ad[NN * 4];
__device__ __align__(16) float g_inv[NN * 4];
__device__ __align__(16) float g_exs[(size_t)NE * 4];
__device__ int   g_deg[NN];
__device__ int   g_off[NN + 1];
__device__ int   g_cur[NN];
__device__ int   g_srcs[NE];
__device__ int   g_pos[NE];
__device__ int   g_bsum[NB];
__device__ int   g_bpre[NB];
__device__ int   g_is64;

struct _Aux {
    cudaStream_t s2 = nullptr;
    cudaEvent_t ev[8] = {};
    bool ok = false;
    _Aux() {
        ok = (cudaStreamCreateWithFlags(&s2, cudaStreamNonBlocking) == cudaSuccess);
        for (int i = 0; i < 8 && ok; i++)
            ok = (cudaEventCreateWithFlags(&ev[i], cudaEventDisableTiming) == cudaSuccess);
    }
};
static _Aux g_aux;

__device__ __forceinline__ float lrelu(float x) { return x > 0.f ? x : 0.2f * x; }

__device__ __forceinline__ int edge_val(const void* ei, size_t idx) {
    int v;
    if (g_is64) v = (int)((const long long*)ei)[idx];
    else        v = ((const int*)ei)[idx];
    return min(max(v, 0), NN - 1);
}

// ---------------- CSR build ----------------
__global__ void k_detzero(const int* __restrict__ w) {
    int i = blockIdx.x * blockDim.x + threadIdx.x;
    if (i < NN) g_deg[i] = 0;
    if (blockIdx.x == 0 && threadIdx.x < 64) {
        __shared__ int cnt;
        if (threadIdx.x == 0) cnt = 0;
        __syncthreads();
        if (w[2 * threadIdx.x + 1] != 0) atomicAdd(&cnt, 1);
        __syncthreads();
        if (threadIdx.x == 0) g_is64 = (cnt == 0) ? 1 : 0;
    } else if (blockIdx.x == 0) {
        __syncthreads();
        __syncthreads();
    }
}

__global__ void k_count(const void* __restrict__ ei) {
    int e = blockIdx.x * blockDim.x + threadIdx.x;
    if (e < NE) atomicAdd(&g_deg[edge_val(ei, (size_t)NE + e)], 1);
}

__global__ void k_scan1() {
    __shared__ int s[256];
    int t = threadIdx.x;
    int i = blockIdx.x * 256 + t;
    int v = (i < NN) ? g_deg[i] : 0;
    s[t] = v;
    __syncthreads();
    for (int o = 1; o < 256; o <<= 1) {
        int add = 0;
        if (t >= o) add = s[t - o];
        __syncthreads();
        s[t] += add;
        __syncthreads();
    }
    if (i < NN) g_off[i] = s[t];
    if (t == 255) g_bsum[blockIdx.x] = s[255];
}

__global__ void k_scan2() {
    __shared__ int s[256];
    int t = threadIdx.x;
    int v = (t < NB) ? g_bsum[t] : 0;
    s[t] = v;
    __syncthreads();
    for (int o = 1; o < 256; o <<= 1) {
        int add = 0;
        if (t >= o) add = s[t - o];
        __syncthreads();
        s[t] += add;
        __syncthreads();
    }
    if (t < NB) g_bpre[t] = s[t] - v;
}

__global__ void k_scan3() {
    int t = threadIdx.x;
    int i = blockIdx.x * 256 + t;
    if (i < NN) {
        int incl = g_off[i] + g_bpre[blockIdx.x];
        int excl = incl - g_deg[i];
        g_off[i] = excl;
        g_cur[i] = excl;
        if (i == NN - 1) g_off[NN] = incl;
    }
}

__global__ void k_scatter(const void* __restrict__ ei) {
    int e = blockIdx.x * blockDim.x + threadIdx.x;
    if (e < NE) {
        int src = edge_val(ei, e);
        int dst = edge_val(ei, (size_t)NE + e);
        int p = atomicAdd(&g_cur[dst], 1);
        g_srcs[p] = src;
        g_pos[e] = p;
    }
}

// ---------------- HMMA GEMM with fused attention-logit epilogue ----------------
__device__ __forceinline__ void hm_load_A(char* smem, const float* __restrict__ X,
                                          int M, int r0, int tid) {
#pragma unroll
    for (int i = 0; i < 16; i++) {
        int lin = i * 256 + tid;
        int row = lin >> 5, c4 = lin & 31;
        float4 v = make_float4(0.f, 0.f, 0.f, 0.f);
        if (r0 + row < M) v = *(const float4*)&X[(size_t)(r0 + row) * 128 + c4 * 4];
        __half2 p0 = __floats2half2_rn(v.x, v.y);
        __half2 p1 = __floats2half2_rn(v.z, v.w);
        uint2 pk;
        pk.x = *(uint32_t*)&p0;
        pk.y = *(uint32_t*)&p1;
        *(uint2*)(smem + HM_A_OFF + row * 272 + c4 * 8) = pk;
    }
}

__device__ __forceinline__ void hm_load_B(char* smem, const float* __restrict__ W,
                                          int ldw, int cb, int tid) {
#pragma unroll
    for (int i = 0; i < 16; i++) {
        int lin = i * 256 + tid;
        int k = lin >> 5, n4 = lin & 31;
        float4 v = *(const float4*)&W[(size_t)k * ldw + cb + n4 * 4];
        __half2 p0 = __floats2half2_rn(v.x, v.y);
        __half2 p1 = __floats2half2_rn(v.z, v.w);
        uint2 pk;
        pk.x = *(uint32_t*)&p0;
        pk.y = *(uint32_t*)&p1;
        *(uint2*)(smem + HM_B_OFF + k * 272 + n4 * 8) = pk;
    }
}

__device__ __forceinline__ void hm_core(uint32_t sA, uint32_t sB, float* __restrict__ C,
                                        int M, int ldw, int r0, int cb, int tid,
                                        const float* __restrict__ asrc,
                                        const float* __restrict__ adst, int C_head) {
    int lane = tid & 31, wid = tid >> 5;
    int wm = wid & 3, wn = wid >> 2;
    float acc[2][8][4];
#pragma unroll
    for (int mt = 0; mt < 2; mt++)
#pragma unroll
        for (int nt = 0; nt < 8; nt++)
#pragma unroll
            for (int c = 0; c < 4; c++) acc[mt][nt][c] = 0.f;

    int arow = wm * 32 + (lane & 15);
    int l16 = (lane >> 4) << 3;

#pragma unroll
    for (int ks = 0; ks < 8; ks++) {
        int k0 = ks * 16;
        uint32_t a[2][4];
#pragma unroll
        for (int mt = 0; mt < 2; mt++) {
            uint32_t addr = sA + (uint32_t)((arow + mt * 16) * 272 + (k0 + l16) * 2);
            LDSM_X4(a[mt][0], a[mt][1], a[mt][2], a[mt][3], addr);
        }
        uint32_t b[8][2];
#pragma unroll
        for (int nt2 = 0; nt2 < 4; nt2++) {
            uint32_t addr = sB + (uint32_t)((k0 + (lane & 15)) * 272 +
                                            (wn * 64 + nt2 * 16 + l16) * 2);
            uint32_t r0_, r1_, r2_, r3_;
            LDSM_X4T(r0_, r1_, r2_, r3_, addr);
            b[nt2 * 2][0] = r0_;     b[nt2 * 2][1] = r1_;
            b[nt2 * 2 + 1][0] = r2_; b[nt2 * 2 + 1][1] = r3_;
        }
#pragma unroll
        for (int mt = 0; mt < 2; mt++)
#pragma unroll
            for (int nt = 0; nt < 8; nt++)
                mma16816(acc[mt][nt], a[mt][0], a[mt][1], a[mt][2], a[mt][3],
                         b[nt][0], b[nt][1]);
    }

#pragma unroll
    for (int mt = 0; mt < 2; mt++) {
        int row = r0 + wm * 32 + mt * 16 + (lane >> 2);
#pragma unroll
        for (int nt = 0; nt < 8; nt++) {
            int col = cb + wn * 64 + nt * 8 + (lane & 3) * 2;
            if (row < M)
                *(float2*)&C[(size_t)row * ldw + col] =
                    make_float2(acc[mt][nt][0], acc[mt][nt][1]);
            if (row + 8 < M)
                *(float2*)&C[(size_t)(row + 8) * ldw + col] =
                    make_float2(acc[mt][nt][2], acc[mt][nt][3]);
        }
    }

    if (C_head) {
        float av0[8], av1[8], dv0[8], dv1[8];
#pragma unroll
        for (int nt = 0; nt < 8; nt++) {
            int col = cb + wn * 64 + nt * 8 + (lane & 3) * 2;
            av0[nt] = asrc[col]; av1[nt] = asrc[col + 1];
            dv0[nt] = adst[col]; dv1[nt] = adst[col + 1];
        }
        int G = (C_head == 32) ? 4 : 8;
        int ngr = 8 / G;
#pragma unroll
        for (int mt = 0; mt < 2; mt++) {
#pragma unroll
            for (int g = 0; g < ngr; g++) {
                float pa0 = 0.f, pd0 = 0.f, pa1 = 0.f, pd1 = 0.f;
#pragma unroll
                for (int q = 0; q < 8; q++) {
                    if ((q / G) == g) {
                        pa0 += acc[mt][q][0] * av0[q] + acc[mt][q][1] * av1[q];
                        pd0 += acc[mt][q][0] * dv0[q] + acc[mt][q][1] * dv1[q];
                        pa1 += acc[mt][q][2] * av0[q] + acc[mt][q][3] * av1[q];
                        pd1 += acc[mt][q][2] * dv0[q] + acc[mt][q][3] * dv1[q];
                    }
                }
                pa0 += __shfl_xor_sync(FULLMASK, pa0, 1);
                pa0 += __shfl_xor_sync(FULLMASK, pa0, 2);
                pd0 += __shfl_xor_sync(FULLMASK, pd0, 1);
                pd0 += __shfl_xor_sync(FULLMASK, pd0, 2);
                pa1 += __shfl_xor_sync(FULLMASK, pa1, 1);
                pa1 += __shfl_xor_sync(FULLMASK, pa1, 2);
                pd1 += __shfl_xor_sync(FULLMASK, pd1, 1);
                pd1 += __shfl_xor_sync(FULLMASK, pd1, 2);
                if ((lane & 3) == 0) {
                    int head = (cb + wn * 64 + g * G * 8) / C_head;
                    int row = r0 + wm * 32 + mt * 16 + (lane >> 2);
                    if (row < M) {
                        g_as[row * 4 + head] = pa0;
                        g_ad[row * 4 + head] = pd0;
                    }
                    if (row + 8 < M) {
                        g_as[(row + 8) * 4 + head] = pa1;
                        g_ad[(row + 8) * 4 + head] = pd1;
                    }
                }
            }
        }
    }
}

__global__ __launch_bounds__(256) void k_gemmhm(const float* __restrict__ X,
                                                const float* __restrict__ W,
                                                float* __restrict__ C, int M, int ldw,
                                                const float* __restrict__ asrc,
                                                const float* __restrict__ adst, int C_head) {
    extern __shared__ char smem[];
    uint32_t sA = smem_to_u32(smem) + HM_A_OFF;
    uint32_t sB = smem_to_u32(smem) + HM_B_OFF;
    int tid = threadIdx.x;
    int r0 = blockIdx.x * 128;
    int cb = blockIdx.y * 128;
    hm_load_A(smem, X, M, r0, tid);
    hm_load_B(smem, W, ldw, cb, tid);
    __syncthreads();
    hm_core(sA, sB, C, M, ldw, r0, cb, tid, asrc, adst, C_head);
}

__global__ __launch_bounds__(256) void k_gemmhm2(const float* __restrict__ X,
                                                 const float* __restrict__ W1,
                                                 float* __restrict__ C1,
                                                 const float* __restrict__ W2,
                                                 float* __restrict__ C2, int M,
                                                 const float* __restrict__ asrc,
                                                 const float* __restrict__ adst) {
    extern __shared__ char smem[];
    uint32_t sA = smem_to_u32(smem) + HM_A_OFF;
    uint32_t sB = smem_to_u32(smem) + HM_B_OFF;
    int tid = threadIdx.x;
    int r0 = blockIdx.x * 128;
    hm_load_A(smem, X, M, r0, tid);
    hm_load_B(smem, W1, 128, 0, tid);
    __syncthreads();
    hm_core(sA, sB, C1, M, 128, r0, 0, tid, asrc, adst, 32);
    __syncthreads();
    hm_load_B(smem, W2, 128, 0, tid);
    __syncthreads();
    hm_core(sA, sB, C2, M, 128, r0, 0, tid, nullptr, nullptr, 0);
}

__device__ __forceinline__ float warp_sum(float v) {
#pragma unroll
    for (int o = 16; o > 0; o >>= 1) v += __shfl_xor_sync(FULLMASK, v, o);
    return v;
}

// ---------------- SINGLE-PASS softmax + aggregation, layers 1/2 ----------------
__global__ __launch_bounds__(256) void k_softagg12(const float* __restrict__ feat,
                                                   const float* __restrict__ bias,
                                                   const float* __restrict__ lnw,
                                                   const float* __restrict__ lnb,
                                                   const float* __restrict__ skip,
                                                   const float* __restrict__ bskip,
                                                   float* __restrict__ outp) {
    int n = blockIdx.x * 8 + (threadIdx.x >> 5);
    int lane = threadIdx.x & 31;
    if (n >= NN) return;
    int beg = g_off[n], end = g_off[n + 1];
    float4 adn = *(const float4*)&g_ad[n * 4];
    int h = lane >> 3;
    float adn_h = (h == 0) ? adn.x : (h == 1) ? adn.y : (h == 2) ? adn.z : adn.w;

    const float4* F = (const float4*)feat;
    float4 acc = make_float4(0.f, 0.f, 0.f, 0.f);
    float sum = 0.f;
    int j = beg;
    // peel to int4 alignment — serial per edge
    for (; j < end && (j & 3); j++) {
        int s = g_srcs[j];
        float a = g_as[s * 4 + h];
        float ex = __expf(fminf(lrelu(a + adn_h), 80.f));
        if ((lane & 7) == 0) {
            g_exs[(size_t)j * 4 + h] = ex;
            sum += ex;
        }
        float4 f = F[(size_t)s * 32 + lane];
        acc.x += ex * f.x; acc.y += ex * f.y; acc.z += ex * f.z; acc.w += ex * f.w;
    }
    for (; j + 8 <= end; j += 8) {
        int4 sv0 = *(const int4*)&g_srcs[j];
        int4 sv1 = *(const int4*)&g_srcs[j + 4];
        int sd = g_srcs[j + (lane & 7)];
        float a = g_as[sd * 4 + h];
        float ex = __expf(fminf(lrelu(a + adn_h), 80.f));
        sum += ex;
        g_exs[(size_t)j * 4 + (lane & 7) * 4 + h] = ex;   // coalesced 128B warp store
        float aa[8];
#pragma unroll
        for (int u = 0; u < 8; u++) aa[u] = __shfl_sync(FULLMASK, ex, (lane & 24) + u);
        int ss[8] = {sv0.x, sv0.y, sv0.z, sv0.w, sv1.x, sv1.y, sv1.z, sv1.w};
        float4 ff[8];
#pragma unroll
        for (int u = 0; u < 8; u++) ff[u] = F[(size_t)ss[u] * 32 + lane];
#pragma unroll
        for (int u = 0; u < 8; u++) {
            acc.x += aa[u] * ff[u].x;
            acc.y += aa[u] * ff[u].y;
            acc.z += aa[u] * ff[u].z;
            acc.w += aa[u] * ff[u].w;
        }
    }
    for (; j < end; j++) {
        int s = g_srcs[j];
        float a = g_as[s * 4 + h];
        float ex = __expf(fminf(lrelu(a + adn_h), 80.f));
        if ((lane & 7) == 0) {
            g_exs[(size_t)j * 4 + h] = ex;
            sum += ex;
        }
        float4 f = F[(size_t)s * 32 + lane];
        acc.x += ex * f.x; acc.y += ex * f.y; acc.z += ex * f.z; acc.w += ex * f.w;
    }
    // per-head sum: each 8-lane group covers all 8 edge residues exactly once
    sum += __shfl_xor_sync(FULLMASK, sum, 1);
    sum += __shfl_xor_sync(FULLMASK, sum, 2);
    sum += __shfl_xor_sync(FULLMASK, sum, 4);
    float invh = 1.f / (sum + 1e-16f);
    float i1 = __shfl_sync(FULLMASK, invh, 8);
    float i2 = __shfl_sync(FULLMASK, invh, 16);
    float i3 = __shfl_sync(FULLMASK, invh, 24);
    if (lane == 0) ((float4*)g_inv)[n] = make_float4(invh, i1, i2, i3);
    acc.x *= invh; acc.y *= invh; acc.z *= invh; acc.w *= invh;

    float4 b4 = ((const float4*)bias)[lane];
    float4 v = make_float4(acc.x + b4.x, acc.y + b4.y, acc.z + b4.z, acc.w + b4.w);
    v.x = v.x > 0.f ? v.x : expm1f(v.x);
    v.y = v.y > 0.f ? v.y : expm1f(v.y);
    v.z = v.z > 0.f ? v.z : expm1f(v.z);
    v.w = v.w > 0.f ? v.w : expm1f(v.w);
    float mu = warp_sum(v.x + v.y + v.z + v.w) * (1.f / 128.f);
    float4 d = make_float4(v.x - mu, v.y - mu, v.z - mu, v.w - mu);
    float var = warp_sum(d.x * d.x + d.y * d.y + d.z * d.z + d.w * d.w) * (1.f / 128.f);
    float rstd = rsqrtf(var + 1e-5f);
    float4 w4 = ((const float4*)lnw)[lane];
    float4 lb = ((const float4*)lnb)[lane];
    float4 y = make_float4(d.x * rstd * w4.x + lb.x, d.y * rstd * w4.y + lb.y,
                           d.z * rstd * w4.z + lb.z, d.w * rstd * w4.w + lb.w);
    if (skip) {
        float4 sk = ((const float4*)skip)[(size_t)n * 32 + lane];
        float4 bs = ((const float4*)bskip)[lane];
        y.x += sk.x + bs.x; y.y += sk.y + bs.y; y.z += sk.z + bs.z; y.w += sk.w + bs.w;
    }
    ((float4*)outp)[(size_t)n * 32 + lane] = y;
}

// ---------------- SINGLE-PASS softmax + aggregation, layer 3 ----------------
__global__ __launch_bounds__(256) void k_softagg3(const float* __restrict__ feat,
                                                  const float* __restrict__ b3,
                                                  float* __restrict__ outp) {
    int n = blockIdx.x * 8 + (threadIdx.x >> 5);
    int lane = threadIdx.x & 31;
    if (n >= NN) return;
    int beg = g_off[n], end = g_off[n + 1];
    float4 adn = *(const float4*)&g_ad[n * 4];
    int hlo = lane >> 4;
    float adl = hlo ? adn.y : adn.x;
    float adh = hlo ? adn.w : adn.z;

    const float4* F = (const float4*)feat;
    float4 acc0 = make_float4(0.f, 0.f, 0.f, 0.f);
    float4 acc1 = make_float4(0.f, 0.f, 0.f, 0.f);
    float suml = 0.f, sumh = 0.f;
    int j = beg;
    for (; j < end && (j & 3); j++) {
        int s = g_srcs[j];
        float al_ = g_as[s * 4 + hlo];
        float ah_ = g_as[s * 4 + 2 + hlo];
        float exl = __expf(fminf(lrelu(al_ + adl), 80.f));
        float exh = __expf(fminf(lrelu(ah_ + adh), 80.f));
        if ((lane & 3) == 0) {
            g_exs[(size_t)j * 4 + hlo] = exl;
            g_exs[(size_t)j * 4 + 2 + hlo] = exh;
            suml += exl; sumh += exh;
        }
        float4 f0 = F[(size_t)s * 64 + lane];
        float4 f1 = F[(size_t)s * 64 + 32 + lane];
        acc0.x += exl * f0.x; acc0.y += exl * f0.y; acc0.z += exl * f0.z; acc0.w += exl * f0.w;
        acc1.x += exh * f1.x; acc1.y += exh * f1.y; acc1.z += exh * f1.z; acc1.w += exh * f1.w;
    }
    for (; j + 4 <= end; j += 4) {
        int4 sv = *(const int4*)&g_srcs[j];
        int sd = g_srcs[j + (lane & 3)];
        float4 a4 = *(const float4*)&g_as[sd * 4];
        float exl = __expf(fminf(lrelu((hlo ? a4.y : a4.x) + adl), 80.f));
        float exh = __expf(fminf(lrelu((hlo ? a4.w : a4.z) + adh), 80.f));
        suml += exl; sumh += exh;
        g_exs[(size_t)(j + (lane & 3)) * 4 + hlo] = exl;
        g_exs[(size_t)(j + (lane & 3)) * 4 + 2 + hlo] = exh;
        float al[4], ah[4];
#pragma unroll
        for (int u = 0; u < 4; u++) {
            al[u] = __shfl_sync(FULLMASK, exl, (lane & 28) + u);
            ah[u] = __shfl_sync(FULLMASK, exh, (lane & 28) + u);
        }
        int ss[4] = {sv.x, sv.y, sv.z, sv.w};
        float4 f0[4], f1[4];
#pragma unroll
        for (int u = 0; u < 4; u++) {
            f0[u] = F[(size_t)ss[u] * 64 + lane];
            f1[u] = F[(size_t)ss[u] * 64 + 32 + lane];
        }
#pragma unroll
        for (int u = 0; u < 4; u++) {
            acc0.x += al[u] * f0[u].x; acc0.y += al[u] * f0[u].y;
            acc0.z += al[u] * f0[u].z; acc0.w += al[u] * f0[u].w;
            acc1.x += ah[u] * f1[u].x; acc1.y += ah[u] * f1[u].y;
            acc1.z += ah[u] * f1[u].z; acc1.w += ah[u] * f1[u].w;
        }
    }
    for (; j < end; j++) {
        int s = g_srcs[j];
        float al_ = g_as[s * 4 + hlo];
        float ah_ = g_as[s * 4 + 2 + hlo];
        float exl = __expf(fminf(lrelu(al_ + adl), 80.f));
        float exh = __expf(fminf(lrelu(ah_ + adh), 80.f));
        if ((lane & 3) == 0) {
            g_exs[(size_t)j * 4 + hlo] = exl;
            g_exs[(size_t)j * 4 + 2 + hlo] = exh;
            suml += exl; sumh += exh;
        }
        float4 f0 = F[(size_t)s * 64 + lane];
        float4 f1 = F[(size_t)s * 64 + 32 + lane];
        acc0.x += exl * f0.x; acc0.y += exl * f0.y; acc0.z += exl * f0.z; acc0.w += exl * f0.w;
        acc1.x += exh * f1.x; acc1.y += exh * f1.y; acc1.z += exh * f1.z; acc1.w += exh * f1.w;
    }
    // each 4-lane group covers all 4 edge residues exactly once
    suml += __shfl_xor_sync(FULLMASK, suml, 1);
    suml += __shfl_xor_sync(FULLMASK, suml, 2);
    sumh += __shfl_xor_sync(FULLMASK, sumh, 1);
    sumh += __shfl_xor_sync(FULLMASK, sumh, 2);
    float invl = 1.f / (suml + 1e-16f);
    float invh = 1.f / (sumh + 1e-16f);
    float i1 = __shfl_sync(FULLMASK, invl, 16);
    float i3 = __shfl_sync(FULLMASK, invh, 16);
    if (lane == 0) ((float4*)g_inv)[n] = make_float4(invl, i1, invh, i3);
    acc0.x *= invl; acc0.y *= invl; acc0.z *= invl; acc0.w *= invl;
    acc1.x *= invh; acc1.y *= invh; acc1.z *= invh; acc1.w *= invh;

    acc0.x += __shfl_down_sync(FULLMASK, acc0.x, 16);
    acc0.y += __shfl_down_sync(FULLMASK, acc0.y, 16);
    acc0.z += __shfl_down_sync(FULLMASK, acc0.z, 16);
    acc0.w += __shfl_down_sync(FULLMASK, acc0.w, 16);
    acc1.x += __shfl_down_sync(FULLMASK, acc1.x, 16);
    acc1.y += __shfl_down_sync(FULLMASK, acc1.y, 16);
    acc1.z += __shfl_down_sync(FULLMASK, acc1.z, 16);
    acc1.w += __shfl_down_sync(FULLMASK, acc1.w, 16);
    if (lane < 16) {
        float4 bb = ((const float4*)b3)[lane];
        float4 r;
        r.x = (acc0.x + acc1.x) * 0.25f + bb.x;
        r.y = (acc0.y + acc1.y) * 0.25f + bb.y;
        r.z = (acc0.z + acc1.z) * 0.25f + bb.z;
        r.w = (acc0.w + acc1.w) * 0.25f + bb.w;
        ((float4*)outp)[(size_t)n * 16 + lane] = r;
    }
}

__global__ void k_alpha(const void* __restrict__ ei, float* __restrict__ alpha_out) {
    int e = blockIdx.x * blockDim.x + threadIdx.x;
    if (e < NE) {
        int p = g_pos[e];
        int dst = edge_val(ei, (size_t)NE + e);
        float4 ex = ((const float4*)g_exs)[p];
        float4 iv = ((const float4*)g_inv)[dst];
        ex.x *= iv.x; ex.y *= iv.y; ex.z *= iv.z; ex.w *= iv.w;
        ((float4*)alpha_out)[e] = ex;
    }
}

// ---------------- host ----------------
extern "C" void kernel_launch(void* const* d_in, const int* in_sizes, int n_in,
                              void* d_out, int out_size) {
    const float* x    = (const float*)d_in[0];
    const void*  ei   = d_in[1];
    const float* W1   = (const float*)d_in[2];
    const float* as1  = (const float*)d_in[3];
    const float* ad1  = (const float*)d_in[4];
    const float* b1   = (const float*)d_in[5];
    const float* ln1w = (const float*)d_in[6];
    const float* ln1b = (const float*)d_in[7];
    const float* Wsk  = (const float*)d_in[8];
    const float* bsk  = (const float*)d_in[9];
    const float* W2   = (const float*)d_in[10];
    const float* as2  = (const float*)d_in[11];
    const float* ad2  = (const float*)d_in[12];
    const float* b2   = (const float*)d_in[13];
    const float* ln2w = (const float*)d_in[14];
    const float* ln2b = (const float*)d_in[15];
    const float* W3   = (const float*)d_in[16];
    const float* as3  = (const float*)d_in[17];
    const float* ad3  = (const float*)d_in[18];
    const float* b3   = (const float*)d_in[19];

    float* out = (float*)d_out;
    float* A1 = out + (size_t)NN * 64;
    float* A2 = A1 + (size_t)NE * 4;
    float* A3 = A2 + (size_t)NE * 4;

    cudaFuncSetAttribute((const void*)k_gemmhm,
                         cudaFuncAttributeMaxDynamicSharedMemorySize, HM_SMEM_TOTAL);
    cudaFuncSetAttribute((const void*)k_gemmhm2,
                         cudaFuncAttributeMaxDynamicSharedMemorySize, HM_SMEM_TOTAL);

    void *ph, *px1, *px2, *psk;
    cudaGetSymbolAddress(&ph, g_h);
    cudaGetSymbolAddress(&px1, g_x1);
    cudaGetSymbolAddress(&px2, g_x2);
    cudaGetSymbolAddress(&psk, g_skip);
    float* fh  = (float*)ph;
    float* fx1 = (float*)px1;
    float* fx2 = (float*)px2;
    float* fsk = (float*)psk;

    dim3 tgrid((NN + 127) / 128, 1);
    dim3 tgrid3((NN + 127) / 128, 2);
    int agrid = (NN + 7) / 8;
    int egrid = (NE + 255) / 256;
    int ngrid = (NN + 255) / 256;

    if (g_aux.ok) {
        cudaStream_t s2 = g_aux.s2;
        cudaEventRecord(g_aux.ev[0], 0);
        cudaStreamWaitEvent(s2, g_aux.ev[0], 0);
        k_detzero<<<ngrid, 256, 0, s2>>>((const int*)ei);
        k_count<<<egrid, 256, 0, s2>>>(ei);
        k_scan1<<<NB, 256, 0, s2>>>();
        k_scan2<<<1, 256, 0, s2>>>();
        k_scan3<<<NB, 256, 0, s2>>>();
        k_scatter<<<egrid, 256, 0, s2>>>(ei);
        cudaEventRecord(g_aux.ev[1], s2);

        k_gemmhm2<<<tgrid, 256, HM_SMEM_TOTAL>>>(x, W1, fh, Wsk, fsk, NN, as1, ad1);
        cudaStreamWaitEvent(0, g_aux.ev[1], 0);
        k_softagg12<<<agrid, 256>>>(fh, b1, ln1w, ln1b, fsk, bsk, fx1);
        cudaEventRecord(g_aux.ev[2], 0);

        cudaStreamWaitEvent(s2, g_aux.ev[2], 0);
        k_alpha<<<egrid, 256, 0, s2>>>(ei, A1);
        cudaEventRecord(g_aux.ev[3], s2);

        k_gemmhm<<<tgrid, 256, HM_SMEM_TOTAL>>>(fx1, W2, fh, NN, 128, as2, ad2, 32);
        cudaStreamWaitEvent(0, g_aux.ev[3], 0);
        k_softagg12<<<agrid, 256>>>(fh, b2, ln2w, ln2b, nullptr, nullptr, fx2);
        cudaEventRecord(g_aux.ev[4], 0);

        cudaStreamWaitEvent(s2, g_aux.ev[4], 0);
        k_alpha<<<egrid, 256, 0, s2>>>(ei, A2);
        cudaEventRecord(g_aux.ev[5], s2);

        k_gemmhm<<<tgrid3, 256, HM_SMEM_TOTAL>>>(fx2, W3, fh, NN, 256, as3, ad3, 64);
        cudaStreamWaitEvent(0, g_aux.ev[5], 0);
        k_softagg3<<<agrid, 256>>>(fh, b3, out);
        cudaEventRecord(g_aux.ev[6], 0);

        cudaStreamWaitEvent(s2, g_aux.ev[6], 0);
        k_alpha<<<egrid, 256, 0, s2>>>(ei, A3);
        cudaEventRecord(g_aux.ev[7], s2);
        cudaStreamWaitEvent(0, g_aux.ev[7], 0);
    } else {
        k_detzero<<<ngrid, 256>>>((const int*)ei);
        k_count<<<egrid, 256>>>(ei);
        k_scan1<<<NB, 256>>>();
        k_scan2<<<1, 256>>>();
        k_scan3<<<NB, 256>>>();
        k_scatter<<<egrid, 256>>>(ei);
        k_gemmhm2<<<tgrid, 256, HM_SMEM_TOTAL>>>(x, W1, fh, Wsk, fsk, NN, as1, ad1);
        k_softagg12<<<agrid, 256>>>(fh, b1, ln1w, ln1b, fsk, bsk, fx1);
        k_alpha<<<egrid, 256>>>(ei, A1);
        k_gemmhm<<<tgrid, 256, HM_SMEM_TOTAL>>>(fx1, W2, fh, NN, 128, as2, ad2, 32);
        k_softagg12<<<agrid, 256>>>(fh, b2, ln2w, ln2b, nullptr, nullptr, fx2);
        k_alpha<<<egrid, 256>>>(ei, A2);
        k_gemmhm<<<tgrid3, 256, HM_SMEM_TOTAL>>>(fx2, W3, fh, NN, 256, as3, ad3, 64);
        k_softagg3<<<agrid, 256>>>(fh, b3, out);
        k_alpha<<<egrid, 256>>>(ei, A3);
    }
}

// round 16
// speedup vs baseline: 1.1145x; 1.1145x over previous
#include <cuda_runtime.h>
#include <cuda_fp16.h>
#include <cstdint>

#define NN 50000
#define NE 1600000
#define NB 196                  // ceil(NN/256)
#define FULLMASK 0xffffffffu

// ---------------- HMMA (mma.sync) helpers — portable sm_80+ features ----------------
__device__ __forceinline__ uint32_t smem_to_u32(const void* p) {
    uint32_t a;
    asm("{ .reg .u64 t; cvta.to.shared.u64 t, %1; cvt.u32.u64 %0, t; }" : "=r"(a) : "l"(p));
    return a;
}
#define LDSM_X4(r0, r1, r2, r3, addr) \
    asm volatile("ldmatrix.sync.aligned.m8n8.x4.shared.b16 {%0,%1,%2,%3}, [%4];" \
                 : "=r"(r0), "=r"(r1), "=r"(r2), "=r"(r3) : "r"(addr))
#define LDSM_X4T(r0, r1, r2, r3, addr) \
    asm volatile("ldmatrix.sync.aligned.m8n8.x4.trans.shared.b16 {%0,%1,%2,%3}, [%4];" \
                 : "=r"(r0), "=r"(r1), "=r"(r2), "=r"(r3) : "r"(addr))

__device__ __forceinline__ void mma16816(float* c, uint32_t a0, uint32_t a1, uint32_t a2,
                                         uint32_t a3, uint32_t b0, uint32_t b1) {
    asm volatile(
        "mma.sync.aligned.m16n8k16.row.col.f32.f16.f16.f32 "
        "{%0,%1,%2,%3}, {%4,%5,%6,%7}, {%8,%9}, {%0,%1,%2,%3};"
        : "+f"(c[0]), "+f"(c[1]), "+f"(c[2]), "+f"(c[3])
        : "r"(a0), "r"(a1), "r"(a2), "r"(a3), "r"(b0), "r"(b1));
}

#define HM_A_OFF 0
#define HM_B_OFF (128 * 272)
#define HM_SMEM_TOTAL (2 * 128 * 272)

// fp16x4 -> float4
__device__ __forceinline__ float4 h2f4(uint2 u) {
    __half2 a = *(__half2*)&u.x, b = *(__half2*)&u.y;
    float2 fa = __half22float2(a), fb = __half22float2(b);
    return make_float4(fa.x, fa.y, fb.x, fb.y);
}

// ---------------- scratch ----------------
__device__ __align__(16) __half g_hh[(size_t)NN * 256];   // fp16 feature rows
__device__ __align__(16) float g_x1[(size_t)NN * 128];
__device__ __align__(16) float g_x2[(size_t)NN * 128];
__device__ __align__(16) float g_skip[(size_t)NN * 128];
__device__ __align__(16) float g_as[NN * 4];
__device__ __align__(16) float g_ad[NN * 4];
__device__ __align__(16) float g_inv[NN * 4];
__device__ __align__(16) float g_exs[(size_t)NE * 4];
__device__ int   g_deg[NN];
__device__ int   g_off[NN + 1];
__device__ int   g_cur[NN];
__device__ int   g_srcs[NE];
__device__ int   g_pos[NE];
__device__ int   g_bsum[NB];
__device__ int   g_bpre[NB];
__device__ int   g_is64;

struct _Aux {
    cudaStream_t s2 = nullptr;
    cudaEvent_t ev[8] = {};
    bool ok = false;
    _Aux() {
        ok = (cudaStreamCreateWithFlags(&s2, cudaStreamNonBlocking) == cudaSuccess);
        for (int i = 0; i < 8 && ok; i++)
            ok = (cudaEventCreateWithFlags(&ev[i], cudaEventDisableTiming) == cudaSuccess);
    }
};
static _Aux g_aux;

__device__ __forceinline__ float lrelu(float x) { return x > 0.f ? x : 0.2f * x; }

__device__ __forceinline__ int edge_val(const void* ei, size_t idx) {
    int v;
    if (g_is64) v = (int)((const long long*)ei)[idx];
    else        v = ((const int*)ei)[idx];
    return min(max(v, 0), NN - 1);
}

// ---------------- CSR build ----------------
__global__ void k_detzero(const int* __restrict__ w) {
    int i = blockIdx.x * blockDim.x + threadIdx.x;
    if (i < NN) g_deg[i] = 0;
    if (blockIdx.x == 0 && threadIdx.x < 64) {
        __shared__ int cnt;
        if (threadIdx.x == 0) cnt = 0;
        __syncthreads();
        if (w[2 * threadIdx.x + 1] != 0) atomicAdd(&cnt, 1);
        __syncthreads();
        if (threadIdx.x == 0) g_is64 = (cnt == 0) ? 1 : 0;
    } else if (blockIdx.x == 0) {
        __syncthreads();
        __syncthreads();
    }
}

__global__ void k_count(const void* __restrict__ ei) {
    int e = blockIdx.x * blockDim.x + threadIdx.x;
    if (e < NE) atomicAdd(&g_deg[edge_val(ei, (size_t)NE + e)], 1);
}

__global__ void k_scan1() {
    __shared__ int s[256];
    int t = threadIdx.x;
    int i = blockIdx.x * 256 + t;
    int v = (i < NN) ? g_deg[i] : 0;
    s[t] = v;
    __syncthreads();
    for (int o = 1; o < 256; o <<= 1) {
        int add = 0;
        if (t >= o) add = s[t - o];
        __syncthreads();
        s[t] += add;
        __syncthreads();
    }
    if (i < NN) g_off[i] = s[t];
    if (t == 255) g_bsum[blockIdx.x] = s[255];
}

__global__ void k_scan2() {
    __shared__ int s[256];
    int t = threadIdx.x;
    int v = (t < NB) ? g_bsum[t] : 0;
    s[t] = v;
    __syncthreads();
    for (int o = 1; o < 256; o <<= 1) {
        int add = 0;
        if (t >= o) add = s[t - o];
        __syncthreads();
        s[t] += add;
        __syncthreads();
    }
    if (t < NB) g_bpre[t] = s[t] - v;
}

__global__ void k_scan3() {
    int t = threadIdx.x;
    int i = blockIdx.x * 256 + t;
    if (i < NN) {
        int incl = g_off[i] + g_bpre[blockIdx.x];
        int excl = incl - g_deg[i];
        g_off[i] = excl;
        g_cur[i] = excl;
        if (i == NN - 1) g_off[NN] = incl;
    }
}

__global__ void k_scatter(const void* __restrict__ ei) {
    int e = blockIdx.x * blockDim.x + threadIdx.x;
    if (e < NE) {
        int src = edge_val(ei, e);
        int dst = edge_val(ei, (size_t)NE + e);
        int p = atomicAdd(&g_cur[dst], 1);
        g_srcs[p] = src;
        g_pos[e] = p;
    }
}

// ---------------- HMMA GEMM with fused attention-logit epilogue ----------------
__device__ __forceinline__ void hm_load_A(char* smem, const float* __restrict__ X,
                                          int M, int r0, int tid) {
#pragma unroll
    for (int i = 0; i < 16; i++) {
        int lin = i * 256 + tid;
        int row = lin >> 5, c4 = lin & 31;
        float4 v = make_float4(0.f, 0.f, 0.f, 0.f);
        if (r0 + row < M) v = *(const float4*)&X[(size_t)(r0 + row) * 128 + c4 * 4];
        __half2 p0 = __floats2half2_rn(v.x, v.y);
        __half2 p1 = __floats2half2_rn(v.z, v.w);
        uint2 pk;
        pk.x = *(uint32_t*)&p0;
        pk.y = *(uint32_t*)&p1;
        *(uint2*)(smem + HM_A_OFF + row * 272 + c4 * 8) = pk;
    }
}

__device__ __forceinline__ void hm_load_B(char* smem, const float* __restrict__ W,
                                          int ldw, int cb, int tid) {
#pragma unroll
    for (int i = 0; i < 16; i++) {
        int lin = i * 256 + tid;
        int k = lin >> 5, n4 = lin & 31;
        float4 v = *(const float4*)&W[(size_t)k * ldw + cb + n4 * 4];
        __half2 p0 = __floats2half2_rn(v.x, v.y);
        __half2 p1 = __floats2half2_rn(v.z, v.w);
        uint2 pk;
        pk.x = *(uint32_t*)&p0;
        pk.y = *(uint32_t*)&p1;
        *(uint2*)(smem + HM_B_OFF + k * 272 + n4 * 8) = pk;
    }
}

// Output: Cf (fp32) XOR Ch (fp16). C_head: 0 = no attn epilogue.
__device__ __forceinline__ void hm_core(uint32_t sA, uint32_t sB,
                                        float* __restrict__ Cf,
                                        __half* __restrict__ Ch,
                                        int M, int ldw, int r0, int cb, int tid,
                                        const float* __restrict__ asrc,
                                        const float* __restrict__ adst, int C_head) {
    int lane = tid & 31, wid = tid >> 5;
    int wm = wid & 3, wn = wid >> 2;
    float acc[2][8][4];
#pragma unroll
    for (int mt = 0; mt < 2; mt++)
#pragma unroll
        for (int nt = 0; nt < 8; nt++)
#pragma unroll
            for (int c = 0; c < 4; c++) acc[mt][nt][c] = 0.f;

    int arow = wm * 32 + (lane & 15);
    int l16 = (lane >> 4) << 3;

#pragma unroll
    for (int ks = 0; ks < 8; ks++) {
        int k0 = ks * 16;
        uint32_t a[2][4];
#pragma unroll
        for (int mt = 0; mt < 2; mt++) {
            uint32_t addr = sA + (uint32_t)((arow + mt * 16) * 272 + (k0 + l16) * 2);
            LDSM_X4(a[mt][0], a[mt][1], a[mt][2], a[mt][3], addr);
        }
        uint32_t b[8][2];
#pragma unroll
        for (int nt2 = 0; nt2 < 4; nt2++) {
            uint32_t addr = sB + (uint32_t)((k0 + (lane & 15)) * 272 +
                                            (wn * 64 + nt2 * 16 + l16) * 2);
            uint32_t r0_, r1_, r2_, r3_;
            LDSM_X4T(r0_, r1_, r2_, r3_, addr);
            b[nt2 * 2][0] = r0_;     b[nt2 * 2][1] = r1_;
            b[nt2 * 2 + 1][0] = r2_; b[nt2 * 2 + 1][1] = r3_;
        }
#pragma unroll
        for (int mt = 0; mt < 2; mt++)
#pragma unroll
            for (int nt = 0; nt < 8; nt++)
                mma16816(acc[mt][nt], a[mt][0], a[mt][1], a[mt][2], a[mt][3],
                         b[nt][0], b[nt][1]);
    }

#pragma unroll
    for (int mt = 0; mt < 2; mt++) {
        int row = r0 + wm * 32 + mt * 16 + (lane >> 2);
#pragma unroll
        for (int nt = 0; nt < 8; nt++) {
            int col = cb + wn * 64 + nt * 8 + (lane & 3) * 2;
            if (Ch) {
                if (row < M)
                    *(__half2*)&Ch[(size_t)row * ldw + col] =
                        __floats2half2_rn(acc[mt][nt][0], acc[mt][nt][1]);
                if (row + 8 < M)
                    *(__half2*)&Ch[(size_t)(row + 8) * ldw + col] =
                        __floats2half2_rn(acc[mt][nt][2], acc[mt][nt][3]);
            } else {
                if (row < M)
                    *(float2*)&Cf[(size_t)row * ldw + col] =
                        make_float2(acc[mt][nt][0], acc[mt][nt][1]);
                if (row + 8 < M)
                    *(float2*)&Cf[(size_t)(row + 8) * ldw + col] =
                        make_float2(acc[mt][nt][2], acc[mt][nt][3]);
            }
        }
    }

    if (C_head) {
        float av0[8], av1[8], dv0[8], dv1[8];
#pragma unroll
        for (int nt = 0; nt < 8; nt++) {
            int col = cb + wn * 64 + nt * 8 + (lane & 3) * 2;
            av0[nt] = asrc[col]; av1[nt] = asrc[col + 1];
            dv0[nt] = adst[col]; dv1[nt] = adst[col + 1];
        }
        int G = (C_head == 32) ? 4 : 8;
        int ngr = 8 / G;
#pragma unroll
        for (int mt = 0; mt < 2; mt++) {
#pragma unroll
            for (int g = 0; g < ngr; g++) {
                float pa0 = 0.f, pd0 = 0.f, pa1 = 0.f, pd1 = 0.f;
#pragma unroll
                for (int q = 0; q < 8; q++) {
                    if ((q / G) == g) {
                        pa0 += acc[mt][q][0] * av0[q] + acc[mt][q][1] * av1[q];
                        pd0 += acc[mt][q][0] * dv0[q] + acc[mt][q][1] * dv1[q];
                        pa1 += acc[mt][q][2] * av0[q] + acc[mt][q][3] * av1[q];
                        pd1 += acc[mt][q][2] * dv0[q] + acc[mt][q][3] * dv1[q];
                    }
                }
                pa0 += __shfl_xor_sync(FULLMASK, pa0, 1);
                pa0 += __shfl_xor_sync(FULLMASK, pa0, 2);
                pd0 += __shfl_xor_sync(FULLMASK, pd0, 1);
                pd0 += __shfl_xor_sync(FULLMASK, pd0, 2);
                pa1 += __shfl_xor_sync(FULLMASK, pa1, 1);
                pa1 += __shfl_xor_sync(FULLMASK, pa1, 2);
                pd1 += __shfl_xor_sync(FULLMASK, pd1, 1);
                pd1 += __shfl_xor_sync(FULLMASK, pd1, 2);
                if ((lane & 3) == 0) {
                    int head = (cb + wn * 64 + g * G * 8) / C_head;
                    int row = r0 + wm * 32 + mt * 16 + (lane >> 2);
                    if (row < M) {
                        g_as[row * 4 + head] = pa0;
                        g_ad[row * 4 + head] = pd0;
                    }
                    if (row + 8 < M) {
                        g_as[(row + 8) * 4 + head] = pa1;
                        g_ad[(row + 8) * 4 + head] = pd1;
                    }
                }
            }
        }
    }
}

__global__ __launch_bounds__(256) void k_gemmhm(const float* __restrict__ X,
                                                const float* __restrict__ W,
                                                __half* __restrict__ Ch, int M, int ldw,
                                                const float* __restrict__ asrc,
                                                const float* __restrict__ adst, int C_head) {
    extern __shared__ char smem[];
    uint32_t sA = smem_to_u32(smem) + HM_A_OFF;
    uint32_t sB = smem_to_u32(smem) + HM_B_OFF;
    int tid = threadIdx.x;
    int r0 = blockIdx.x * 128;
    int cb = blockIdx.y * 128;
    hm_load_A(smem, X, M, r0, tid);
    hm_load_B(smem, W, ldw, cb, tid);
    __syncthreads();
    hm_core(sA, sB, nullptr, Ch, M, ldw, r0, cb, tid, asrc, adst, C_head);
}

// layer 1: W1 -> fp16 features (+attn), Wskip -> fp32 skip
__global__ __launch_bounds__(256) void k_gemmhm2(const float* __restrict__ X,
                                                 const float* __restrict__ W1,
                                                 __half* __restrict__ C1,
                                                 const float* __restrict__ W2,
                                                 float* __restrict__ C2, int M,
                                                 const float* __restrict__ asrc,
                                                 const float* __restrict__ adst) {
    extern __shared__ char smem[];
    uint32_t sA = smem_to_u32(smem) + HM_A_OFF;
    uint32_t sB = smem_to_u32(smem) + HM_B_OFF;
    int tid = threadIdx.x;
    int r0 = blockIdx.x * 128;
    hm_load_A(smem, X, M, r0, tid);
    hm_load_B(smem, W1, 128, 0, tid);
    __syncthreads();
    hm_core(sA, sB, nullptr, C1, M, 128, r0, 0, tid, asrc, adst, 32);
    __syncthreads();
    hm_load_B(smem, W2, 128, 0, tid);
    __syncthreads();
    hm_core(sA, sB, C2, nullptr, M, 128, r0, 0, tid, nullptr, nullptr, 0);
}

// ---------------- single-pass softmax (R14) ----------------
__device__ __forceinline__ void softmax_phase(int beg, int end, int lane, float4 adn,
                                              float4& inv) {
    float4 sm = make_float4(0.f, 0.f, 0.f, 0.f);
    float4* EX = (float4*)g_exs;
    for (int j = beg + lane; j < end; j += 32) {
        int s = g_srcs[j];
        float4 a = *(const float4*)&g_as[s * 4];
        float4 ex;
        ex.x = __expf(fminf(lrelu(a.x + adn.x), 80.f));
        ex.y = __expf(fminf(lrelu(a.y + adn.y), 80.f));
        ex.z = __expf(fminf(lrelu(a.z + adn.z), 80.f));
        ex.w = __expf(fminf(lrelu(a.w + adn.w), 80.f));
        EX[j] = ex;
        sm.x += ex.x; sm.y += ex.y; sm.z += ex.z; sm.w += ex.w;
    }
#pragma unroll
    for (int o = 16; o > 0; o >>= 1) {
        sm.x += __shfl_xor_sync(FULLMASK, sm.x, o);
        sm.y += __shfl_xor_sync(FULLMASK, sm.y, o);
        sm.z += __shfl_xor_sync(FULLMASK, sm.z, o);
        sm.w += __shfl_xor_sync(FULLMASK, sm.w, o);
    }
    inv.x = 1.f / (sm.x + 1e-16f);
    inv.y = 1.f / (sm.y + 1e-16f);
    inv.z = 1.f / (sm.z + 1e-16f);
    inv.w = 1.f / (sm.w + 1e-16f);
    __syncwarp();
}

__device__ __forceinline__ float warp_sum(float v) {
#pragma unroll
    for (int o = 16; o > 0; o >>= 1) v += __shfl_xor_sync(FULLMASK, v, o);
    return v;
}

// layers 1/2: 128 fp16 channels
__global__ __launch_bounds__(256) void k_softagg12(const __half* __restrict__ feat,
                                                   const float* __restrict__ bias,
                                                   const float* __restrict__ lnw,
                                                   const float* __restrict__ lnb,
                                                   const float* __restrict__ skip,
                                                   const float* __restrict__ bskip,
                                                   float* __restrict__ outp) {
    int n = blockIdx.x * 8 + (threadIdx.x >> 5);
    int lane = threadIdx.x & 31;
    if (n >= NN) return;
    int beg = g_off[n], end = g_off[n + 1];
    float4 adn = *(const float4*)&g_ad[n * 4];
    float4 inv;
    softmax_phase(beg, end, lane, adn, inv);
    if (lane == 0) ((float4*)g_inv)[n] = inv;

    int h = lane >> 3;
    const uint2* F = (const uint2*)feat;          // row = 32 uint2 (128 ch fp16)
    const float4* EX = (const float4*)g_exs;
    float4 acc = make_float4(0.f, 0.f, 0.f, 0.f);
    int j = beg;
    for (; j < end && (j & 3); j++) {
        int s = g_srcs[j];
        float a = g_exs[(size_t)j * 4 + h];
        float4 f = h2f4(F[(size_t)s * 32 + lane]);
        acc.x += a * f.x; acc.y += a * f.y; acc.z += a * f.z; acc.w += a * f.w;
    }
    for (; j + 8 <= end; j += 8) {
        int4 sv0 = *(const int4*)&g_srcs[j];
        int4 sv1 = *(const int4*)&g_srcs[j + 4];
        float4 af = EX[j + (lane & 7)];
        float c = (h == 0) ? af.x : (h == 1) ? af.y : (h == 2) ? af.z : af.w;
        int src_base = lane & 24;
        float aa[8];
#pragma unroll
        for (int u = 0; u < 8; u++) aa[u] = __shfl_sync(FULLMASK, c, src_base + u);
        int ss[8] = {sv0.x, sv0.y, sv0.z, sv0.w, sv1.x, sv1.y, sv1.z, sv1.w};
        uint2 fraw[8];
#pragma unroll
        for (int u = 0; u < 8; u++) fraw[u] = F[(size_t)ss[u] * 32 + lane];
#pragma unroll
        for (int u = 0; u < 8; u++) {
            float4 f = h2f4(fraw[u]);
            acc.x += aa[u] * f.x;
            acc.y += aa[u] * f.y;
            acc.z += aa[u] * f.z;
            acc.w += aa[u] * f.w;
        }
    }
    for (; j < end; j++) {
        int s = g_srcs[j];
        float a = g_exs[(size_t)j * 4 + h];
        float4 f = h2f4(F[(size_t)s * 32 + lane]);
        acc.x += a * f.x; acc.y += a * f.y; acc.z += a * f.z; acc.w += a * f.w;
    }
    float invh = (h == 0) ? inv.x : (h == 1) ? inv.y : (h == 2) ? inv.z : inv.w;
    acc.x *= invh; acc.y *= invh; acc.z *= invh; acc.w *= invh;

    float4 b4 = ((const float4*)bias)[lane];
    float4 v = make_float4(acc.x + b4.x, acc.y + b4.y, acc.z + b4.z, acc.w + b4.w);
    v.x = v.x > 0.f ? v.x : expm1f(v.x);
    v.y = v.y > 0.f ? v.y : expm1f(v.y);
    v.z = v.z > 0.f ? v.z : expm1f(v.z);
    v.w = v.w > 0.f ? v.w : expm1f(v.w);
    float mu = warp_sum(v.x + v.y + v.z + v.w) * (1.f / 128.f);
    float4 d = make_float4(v.x - mu, v.y - mu, v.z - mu, v.w - mu);
    float var = warp_sum(d.x * d.x + d.y * d.y + d.z * d.z + d.w * d.w) * (1.f / 128.f);
    float rstd = rsqrtf(var + 1e-5f);
    float4 w4 = ((const float4*)lnw)[lane];
    float4 lb = ((const float4*)lnb)[lane];
    float4 y = make_float4(d.x * rstd * w4.x + lb.x, d.y * rstd * w4.y + lb.y,
                           d.z * rstd * w4.z + lb.z, d.w * rstd * w4.w + lb.w);
    if (skip) {
        float4 sk = ((const float4*)skip)[(size_t)n * 32 + lane];
        float4 bs = ((const float4*)bskip)[lane];
        y.x += sk.x + bs.x; y.y += sk.y + bs.y; y.z += sk.z + bs.z; y.w += sk.w + bs.w;
    }
    ((float4*)outp)[(size_t)n * 32 + lane] = y;
}

// layer 3: 256 fp16 channels, head-mean + bias -> out[N,64]
__global__ __launch_bounds__(256) void k_softagg3(const __half* __restrict__ feat,
                                                  const float* __restrict__ b3,
                                                  float* __restrict__ outp) {
    int n = blockIdx.x * 8 + (threadIdx.x >> 5);
    int lane = threadIdx.x & 31;
    if (n >= NN) return;
    int beg = g_off[n], end = g_off[n + 1];
    float4 adn = *(const float4*)&g_ad[n * 4];
    float4 inv;
    softmax_phase(beg, end, lane, adn, inv);
    if (lane == 0) ((float4*)g_inv)[n] = inv;

    int hlo = lane >> 4;
    const uint2* F = (const uint2*)feat;          // row = 64 uint2 (256 ch fp16)
    const float4* EX = (const float4*)g_exs;
    float4 acc0 = make_float4(0.f, 0.f, 0.f, 0.f);
    float4 acc1 = make_float4(0.f, 0.f, 0.f, 0.f);
    int j = beg;
    for (; j < end && (j & 3); j++) {
        int s = g_srcs[j];
        float al = g_exs[(size_t)j * 4 + hlo];
        float ah = g_exs[(size_t)j * 4 + 2 + hlo];
        float4 f0 = h2f4(F[(size_t)s * 64 + lane]);
        float4 f1 = h2f4(F[(size_t)s * 64 + 32 + lane]);
        acc0.x += al * f0.x; acc0.y += al * f0.y; acc0.z += al * f0.z; acc0.w += al * f0.w;
        acc1.x += ah * f1.x; acc1.y += ah * f1.y; acc1.z += ah * f1.z; acc1.w += ah * f1.w;
    }
    for (; j + 4 <= end; j += 4) {
        int4 sv = *(const int4*)&g_srcs[j];
        float4 af = EX[j + (lane & 3)];
        float cl = hlo ? af.y : af.x;
        float ch = hlo ? af.w : af.z;
        int src_base = lane & 28;
        float al[4], ah[4];
#pragma unroll
        for (int u = 0; u < 4; u++) {
            al[u] = __shfl_sync(FULLMASK, cl, src_base + u);
            ah[u] = __shfl_sync(FULLMASK, ch, src_base + u);
        }
        int ss[4] = {sv.x, sv.y, sv.z, sv.w};
        uint2 fr0[4], fr1[4];
#pragma unroll
        for (int u = 0; u < 4; u++) {
            fr0[u] = F[(size_t)ss[u] * 64 + lane];
            fr1[u] = F[(size_t)ss[u] * 64 + 32 + lane];
        }
#pragma unroll
        for (int u = 0; u < 4; u++) {
            float4 f0 = h2f4(fr0[u]);
            float4 f1 = h2f4(fr1[u]);
            acc0.x += al[u] * f0.x; acc0.y += al[u] * f0.y;
            acc0.z += al[u] * f0.z; acc0.w += al[u] * f0.w;
            acc1.x += ah[u] * f1.x; acc1.y += ah[u] * f1.y;
            acc1.z += ah[u] * f1.z; acc1.w += ah[u] * f1.w;
        }
    }
    for (; j < end; j++) {
        int s = g_srcs[j];
        float al = g_exs[(size_t)j * 4 + hlo];
        float ah = g_exs[(size_t)j * 4 + 2 + hlo];
        float4 f0 = h2f4(F[(size_t)s * 64 + lane]);
        float4 f1 = h2f4(F[(size_t)s * 64 + 32 + lane]);
        acc0.x += al * f0.x; acc0.y += al * f0.y; acc0.z += al * f0.z; acc0.w += al * f0.w;
        acc1.x += ah * f1.x; acc1.y += ah * f1.y; acc1.z += ah * f1.z; acc1.w += ah * f1.w;
    }
    float invlo = hlo ? inv.y : inv.x;
    float invhi = hlo ? inv.w : inv.z;
    acc0.x *= invlo; acc0.y *= invlo; acc0.z *= invlo; acc0.w *= invlo;
    acc1.x *= invhi; acc1.y *= invhi; acc1.z *= invhi; acc1.w *= invhi;

    acc0.x += __shfl_down_sync(FULLMASK, acc0.x, 16);
    acc0.y += __shfl_down_sync(FULLMASK, acc0.y, 16);
    acc0.z += __shfl_down_sync(FULLMASK, acc0.z, 16);
    acc0.w += __shfl_down_sync(FULLMASK, acc0.w, 16);
    acc1.x += __shfl_down_sync(FULLMASK, acc1.x, 16);
    acc1.y += __shfl_down_sync(FULLMASK, acc1.y, 16);
    acc1.z += __shfl_down_sync(FULLMASK, acc1.z, 16);
    acc1.w += __shfl_down_sync(FULLMASK, acc1.w, 16);
    if (lane < 16) {
        float4 bb = ((const float4*)b3)[lane];
        float4 r;
        r.x = (acc0.x + acc1.x) * 0.25f + bb.x;
        r.y = (acc0.y + acc1.y) * 0.25f + bb.y;
        r.z = (acc0.z + acc1.z) * 0.25f + bb.z;
        r.w = (acc0.w + acc1.w) * 0.25f + bb.w;
        ((float4*)outp)[(size_t)n * 16 + lane] = r;
    }
}

__global__ void k_alpha(const void* __restrict__ ei, float* __restrict__ alpha_out) {
    int e = blockIdx.x * blockDim.x + threadIdx.x;
    if (e < NE) {
        int p = g_pos[e];
        int dst = edge_val(ei, (size_t)NE + e);
        float4 ex = ((const float4*)g_exs)[p];
        float4 iv = ((const float4*)g_inv)[dst];
        ex.x *= iv.x; ex.y *= iv.y; ex.z *= iv.z; ex.w *= iv.w;
        ((float4*)alpha_out)[e] = ex;
    }
}

// ---------------- host ----------------
extern "C" void kernel_launch(void* const* d_in, const int* in_sizes, int n_in,
                              void* d_out, int out_size) {
    const float* x    = (const float*)d_in[0];
    const void*  ei   = d_in[1];
    const float* W1   = (const float*)d_in[2];
    const float* as1  = (const float*)d_in[3];
    const float* ad1  = (const float*)d_in[4];
    const float* b1   = (const float*)d_in[5];
    const float* ln1w = (const float*)d_in[6];
    const float* ln1b = (const float*)d_in[7];
    const float* Wsk  = (const float*)d_in[8];
    const float* bsk  = (const float*)d_in[9];
    const float* W2   = (const float*)d_in[10];
    const float* as2  = (const float*)d_in[11];
    const float* ad2  = (const float*)d_in[12];
    const float* b2   = (const float*)d_in[13];
    const float* ln2w = (const float*)d_in[14];
    const float* ln2b = (const float*)d_in[15];
    const float* W3   = (const float*)d_in[16];
    const float* as3  = (const float*)d_in[17];
    const float* ad3  = (const float*)d_in[18];
    const float* b3   = (const float*)d_in[19];

    float* out = (float*)d_out;
    float* A1 = out + (size_t)NN * 64;
    float* A2 = A1 + (size_t)NE * 4;
    float* A3 = A2 + (size_t)NE * 4;

    cudaFuncSetAttribute((const void*)k_gemmhm,
                         cudaFuncAttributeMaxDynamicSharedMemorySize, HM_SMEM_TOTAL);
    cudaFuncSetAttribute((const void*)k_gemmhm2,
                         cudaFuncAttributeMaxDynamicSharedMemorySize, HM_SMEM_TOTAL);

    void *ph, *px1, *px2, *psk;
    cudaGetSymbolAddress(&ph, g_hh);
    cudaGetSymbolAddress(&px1, g_x1);
    cudaGetSymbolAddress(&px2, g_x2);
    cudaGetSymbolAddress(&psk, g_skip);
    __half* fh = (__half*)ph;
    float* fx1 = (float*)px1;
    float* fx2 = (float*)px2;
    float* fsk = (float*)psk;

    dim3 tgrid((NN + 127) / 128, 1);
    dim3 tgrid3((NN + 127) / 128, 2);
    int agrid = (NN + 7) / 8;
    int egrid = (NE + 255) / 256;
    int ngrid = (NN + 255) / 256;

    if (g_aux.ok) {
        cudaStream_t s2 = g_aux.s2;
        cudaEventRecord(g_aux.ev[0], 0);
        cudaStreamWaitEvent(s2, g_aux.ev[0], 0);
        k_detzero<<<ngrid, 256, 0, s2>>>((const int*)ei);
        k_count<<<egrid, 256, 0, s2>>>(ei);
        k_scan1<<<NB, 256, 0, s2>>>();
        k_scan2<<<1, 256, 0, s2>>>();
        k_scan3<<<NB, 256, 0, s2>>>();
        k_scatter<<<egrid, 256, 0, s2>>>(ei);
        cudaEventRecord(g_aux.ev[1], s2);

        k_gemmhm2<<<tgrid, 256, HM_SMEM_TOTAL>>>(x, W1, fh, Wsk, fsk, NN, as1, ad1);
        cudaStreamWaitEvent(0, g_aux.ev[1], 0);
        k_softagg12<<<agrid, 256>>>(fh, b1, ln1w, ln1b, fsk, bsk, fx1);
        cudaEventRecord(g_aux.ev[2], 0);

        cudaStreamWaitEvent(s2, g_aux.ev[2], 0);
        k_alpha<<<egrid, 256, 0, s2>>>(ei, A1);
        cudaEventRecord(g_aux.ev[3], s2);

        k_gemmhm<<<tgrid, 256, HM_SMEM_TOTAL>>>(fx1, W2, fh, NN, 128, as2, ad2, 32);
        cudaStreamWaitEvent(0, g_aux.ev[3], 0);
        k_softagg12<<<agrid, 256>>>(fh, b2, ln2w, ln2b, nullptr, nullptr, fx2);
        cudaEventRecord(g_aux.ev[4], 0);

        cudaStreamWaitEvent(s2, g_aux.ev[4], 0);
        k_alpha<<<egrid, 256, 0, s2>>>(ei, A2);
        cudaEventRecord(g_aux.ev[5], s2);

        k_gemmhm<<<tgrid3, 256, HM_SMEM_TOTAL>>>(fx2, W3, fh, NN, 256, as3, ad3, 64);
        cudaStreamWaitEvent(0, g_aux.ev[5], 0);
        k_softagg3<<<agrid, 256>>>(fh, b3, out);
        cudaEventRecord(g_aux.ev[6], 0);

        cudaStreamWaitEvent(s2, g_aux.ev[6], 0);
        k_alpha<<<egrid, 256, 0, s2>>>(ei, A3);
        cudaEventRecord(g_aux.ev[7], s2);
        cudaStreamWaitEvent(0, g_aux.ev[7], 0);
    } else {
        k_detzero<<<ngrid, 256>>>((const int*)ei);
        k_count<<<egrid, 256>>>(ei);
        k_scan1<<<NB, 256>>>();
        k_scan2<<<1, 256>>>();
        k_scan3<<<NB, 256>>>();
        k_scatter<<<egrid, 256>>>(ei);
        k_gemmhm2<<<tgrid, 256, HM_SMEM_TOTAL>>>(x, W1, fh, Wsk, fsk, NN, as1, ad1);
        k_softagg12<<<agrid, 256>>>(fh, b1, ln1w, ln1b, fsk, bsk, fx1);
        k_alpha<<<egrid, 256>>>(ei, A1);
        k_gemmhm<<<tgrid, 256, HM_SMEM_TOTAL>>>(fx1, W2, fh, NN, 128, as2, ad2, 32);
        k_softagg12<<<agrid, 256>>>(fh, b2, ln2w, ln2b, nullptr, nullptr, fx2);
        k_alpha<<<egrid, 256>>>(ei, A2);
        k_gemmhm<<<tgrid3, 256, HM_SMEM_TOTAL>>>(fx2, W3, fh, NN, 256, as3, ad3, 64);
        k_softagg3<<<agrid, 256>>>(fh, b3, out);
        k_alpha<<<egrid, 256>>>(ei, A3);
    }
}